// round 1
// baseline (speedup 1.0000x reference)
#include <cuda_runtime.h>
#include <cuda_bf16.h>

// ROI Align (aligned=true, sampling_ratio=2) over 3 FPN levels.
// One thread per (roi, output pixel); geometry (16 tap offsets + weights,
// with the 1/4 sample-mean and validity mask folded in) computed once in
// registers, then a 256-channel loop of 16 LDG + 16 FMA.
//
// Output buffer layout: concat of the three (N,C,P,P) fp32 tensors.

#define RA_THREADS 256

__global__ void __launch_bounds__(RA_THREADS)
roi_align_level_kernel(const float* __restrict__ feat,
                       const float* __restrict__ rois,
                       float* __restrict__ out,
                       int N, int C, int H, int W, int P, float scale)
{
    const int pixels = P * P;
    int tid = blockIdx.x * RA_THREADS + threadIdx.x;
    if (tid >= N * pixels) return;

    int n  = tid / pixels;
    int p  = tid - n * pixels;
    int ph = p / P;
    int pw = p - ph * P;

    const float* r = rois + n * 5;
    int   b  = (int)r[0];
    float x1 = r[1] * scale - 0.5f;
    float y1 = r[2] * scale - 0.5f;
    float x2 = r[3] * scale - 0.5f;
    float y2 = r[4] * scale - 0.5f;
    float bin_h = (y2 - y1) / (float)P;
    float bin_w = (x2 - x1) / (float)P;

    float w[16];
    int   off[16];

    #pragma unroll
    for (int iy = 0; iy < 2; iy++) {
        #pragma unroll
        for (int ix = 0; ix < 2; ix++) {
            float yy = y1 + ((float)ph + ((float)iy + 0.5f) * 0.5f) * bin_h;
            float xx = x1 + ((float)pw + ((float)ix + 0.5f) * 0.5f) * bin_w;
            bool valid = (yy > -1.0f) && (yy < (float)H) &&
                         (xx > -1.0f) && (xx < (float)W);
            float yc = fminf(fmaxf(yy, 0.0f), (float)(H - 1));
            float xc = fminf(fmaxf(xx, 0.0f), (float)(W - 1));
            int y0 = (int)floorf(yc);
            int x0 = (int)floorf(xc);
            int y1i = min(y0 + 1, H - 1);
            int x1i = min(x0 + 1, W - 1);
            float ly = yc - (float)y0;
            float lx = xc - (float)x0;
            float hy = 1.0f - ly;
            float hx = 1.0f - lx;
            float ws = valid ? 0.25f : 0.0f;   // fold sample-mean (/4) + mask
            int k = (iy * 2 + ix) * 4;
            w[k + 0] = hy * hx * ws;  off[k + 0] = y0  * W + x0;
            w[k + 1] = hy * lx * ws;  off[k + 1] = y0  * W + x1i;
            w[k + 2] = ly * hx * ws;  off[k + 2] = y1i * W + x0;
            w[k + 3] = ly * lx * ws;  off[k + 3] = y1i * W + x1i;
        }
    }

    const int HW = H * W;
    const float* fb = feat + (size_t)b * C * HW;
    float*       ob = out  + (size_t)n * C * pixels + p;

    for (int c = 0; c < C; c++) {
        const float* f = fb + (size_t)c * HW;
        float acc = 0.0f;
        #pragma unroll
        for (int k = 0; k < 16; k++)
            acc = fmaf(w[k], __ldg(f + off[k]), acc);
        ob[(size_t)c * pixels] = acc;
    }
}

extern "C" void kernel_launch(void* const* d_in, const int* in_sizes, int n_in,
                              void* d_out, int out_size)
{
    const float* feat1 = (const float*)d_in[0];  // (2,256,256,256)
    const float* feat2 = (const float*)d_in[1];  // (2,256,128,128)
    const float* feat3 = (const float*)d_in[2];  // (2,256,64,64)
    const float* rois  = (const float*)d_in[3];  // (N,5)
    float* out = (float*)d_out;

    const int N = in_sizes[3] / 5;
    const int C = 256;

    float* out1 = out;
    float* out2 = out1 + (size_t)N * C * 28 * 28;
    float* out3 = out2 + (size_t)N * C * 14 * 14;

    {
        int jobs = N * 28 * 28;
        int blocks = (jobs + RA_THREADS - 1) / RA_THREADS;
        roi_align_level_kernel<<<blocks, RA_THREADS>>>(
            feat1, rois, out1, N, C, 256, 256, 28, 1.0f / 4.0f);
    }
    {
        int jobs = N * 14 * 14;
        int blocks = (jobs + RA_THREADS - 1) / RA_THREADS;
        roi_align_level_kernel<<<blocks, RA_THREADS>>>(
            feat2, rois, out2, N, C, 128, 128, 14, 1.0f / 8.0f);
    }
    {
        int jobs = N * 7 * 7;
        int blocks = (jobs + RA_THREADS - 1) / RA_THREADS;
        roi_align_level_kernel<<<blocks, RA_THREADS>>>(
            feat3, rois, out3, N, C, 64, 64, 7, 1.0f / 16.0f);
    }
}

// round 2
// speedup vs baseline: 5.0165x; 5.0165x over previous
#include <cuda_runtime.h>
#include <cuda_bf16.h>

// ROI Align (aligned=true, sampling_ratio=2) over 3 FPN levels, fused into
// ONE kernel launch. Parallelism: one thread per (channel-group, roi, output
// pixel), CPT=8 channels per thread. Geometry computed once per thread:
// 4 sample bases + 16 weights (edge clamps folded into the weight pairs so
// taps are always base, base+1, base+W, base+W+1 with W a compile-time
// constant -> immediate-offset LDGs).

#define RA_THREADS 256
#define CPT 8                 // channels per thread
#define NGROUPS (256 / CPT)   // 32 channel groups

template <int P, int H, int W>
__device__ __forceinline__ void roi_level(const float* __restrict__ feat,
                                          const float* __restrict__ rois,
                                          float* __restrict__ out,
                                          int N, int tid, float scale)
{
    constexpr int pixels = P * P;
    constexpr int HW = H * W;
    constexpr float invP = 1.0f / (float)P;

    const int NP  = N * pixels;
    int g   = tid / NP;            // channel group 0..31
    int rem = tid - g * NP;
    int n   = rem / pixels;
    int p   = rem - n * pixels;
    int ph  = p / P;
    int pw  = p - ph * P;

    const float* r = rois + n * 5;
    int   bi = (int)r[0];
    float x1 = fmaf(r[1], scale, -0.5f);
    float y1 = fmaf(r[2], scale, -0.5f);
    float x2 = fmaf(r[3], scale, -0.5f);
    float y2 = fmaf(r[4], scale, -0.5f);
    float bin_h = (y2 - y1) * invP;
    float bin_w = (x2 - x1) * invP;

    int   base[4];
    float w[16];

    #pragma unroll
    for (int iy = 0; iy < 2; iy++) {
        #pragma unroll
        for (int ix = 0; ix < 2; ix++) {
            float yy = fmaf((float)ph + ((float)iy + 0.5f) * 0.5f, bin_h, y1);
            float xx = fmaf((float)pw + ((float)ix + 0.5f) * 0.5f, bin_w, x1);
            bool valid = (yy > -1.0f) && (yy < (float)H) &&
                         (xx > -1.0f) && (xx < (float)W);
            float yc = fminf(fmaxf(yy, 0.0f), (float)(H - 1));
            float xc = fminf(fmaxf(xx, 0.0f), (float)(W - 1));
            int y0 = (int)yc;            // yc >= 0: trunc == floor
            int x0 = (int)xc;
            float ly = yc - (float)y0;
            float lx = xc - (float)x0;
            // fold right/bottom clamp into the 2-tap weight pair
            float wy1 = (y0 >= H - 1) ? 1.0f : ly;
            float wx1 = (x0 >= W - 1) ? 1.0f : lx;
            float wy0 = 1.0f - wy1;
            float wx0 = 1.0f - wx1;
            int ya = min(y0, H - 2);
            int xa = min(x0, W - 2);
            float ws = valid ? 0.25f : 0.0f;  // sample mean + validity mask
            int s = iy * 2 + ix;
            base[s]     = ya * W + xa;
            w[s * 4 + 0] = wy0 * wx0 * ws;
            w[s * 4 + 1] = wy0 * wx1 * ws;
            w[s * 4 + 2] = wy1 * wx0 * ws;
            w[s * 4 + 3] = wy1 * wx1 * ws;
        }
    }

    const int c0 = g * CPT;
    const float* fb = feat + ((size_t)bi * 256 + c0) * HW;
    float*       ob = out  + ((size_t)n  * 256 + c0) * pixels + p;

    #pragma unroll 2
    for (int i = 0; i < CPT; i++) {
        const float* f = fb + (size_t)i * HW;
        float acc = 0.0f;
        #pragma unroll
        for (int s = 0; s < 4; s++) {
            const float* fp = f + base[s];
            acc = fmaf(w[4 * s + 0], __ldg(fp),         acc);
            acc = fmaf(w[4 * s + 1], __ldg(fp + 1),     acc);
            acc = fmaf(w[4 * s + 2], __ldg(fp + W),     acc);
            acc = fmaf(w[4 * s + 3], __ldg(fp + W + 1), acc);
        }
        ob[(size_t)i * pixels] = acc;
    }
}

__global__ void __launch_bounds__(RA_THREADS)
roi_align_fused_kernel(const float* __restrict__ feat1,
                       const float* __restrict__ feat2,
                       const float* __restrict__ feat3,
                       const float* __restrict__ rois,
                       float* __restrict__ out1,
                       float* __restrict__ out2,
                       float* __restrict__ out3,
                       int N, int b1, int b12)
{
    const int blk = blockIdx.x;
    if (blk < b1) {
        int tid = blk * RA_THREADS + threadIdx.x;
        if (tid < N * 28 * 28 * NGROUPS)
            roi_level<28, 256, 256>(feat1, rois, out1, N, tid, 0.25f);
    } else if (blk < b12) {
        int tid = (blk - b1) * RA_THREADS + threadIdx.x;
        if (tid < N * 14 * 14 * NGROUPS)
            roi_level<14, 128, 128>(feat2, rois, out2, N, tid, 0.125f);
    } else {
        int tid = (blk - b12) * RA_THREADS + threadIdx.x;
        if (tid < N * 7 * 7 * NGROUPS)
            roi_level<7, 64, 64>(feat3, rois, out3, N, tid, 0.0625f);
    }
}

extern "C" void kernel_launch(void* const* d_in, const int* in_sizes, int n_in,
                              void* d_out, int out_size)
{
    const float* feat1 = (const float*)d_in[0];  // (2,256,256,256)
    const float* feat2 = (const float*)d_in[1];  // (2,256,128,128)
    const float* feat3 = (const float*)d_in[2];  // (2,256,64,64)
    const float* rois  = (const float*)d_in[3];  // (N,5)
    float* out = (float*)d_out;

    const int N = in_sizes[3] / 5;
    const int C = 256;

    float* out1 = out;
    float* out2 = out1 + (size_t)N * C * 28 * 28;
    float* out3 = out2 + (size_t)N * C * 14 * 14;

    int jobs1 = N * 28 * 28 * NGROUPS;
    int jobs2 = N * 14 * 14 * NGROUPS;
    int jobs3 = N * 7  * 7  * NGROUPS;
    int b1 = (jobs1 + RA_THREADS - 1) / RA_THREADS;
    int b2 = (jobs2 + RA_THREADS - 1) / RA_THREADS;
    int b3 = (jobs3 + RA_THREADS - 1) / RA_THREADS;

    roi_align_fused_kernel<<<b1 + b2 + b3, RA_THREADS>>>(
        feat1, feat2, feat3, rois, out1, out2, out3, N, b1, b1 + b2);
}

// round 3
// speedup vs baseline: 5.6918x; 1.1346x over previous
#include <cuda_runtime.h>
#include <cuda_fp16.h>

#define NCH 256

// fp16 NHWC copies of the three feature maps:
//   L1: 2 imgs * 65536 cells, L2: 2*16384, L3: 2*4096, each cell * 256 ch.
// offsets (in halves): L1=0, L2=33554432, L3=41943040, total 44040192 (88MB)
__device__ __half g_nhwc[44040192];

// ---------------------------------------------------------------------------
// NCHW fp32 -> NHWC fp16 transpose (per level). Tiles of 32ch x 32cells via
// padded smem. Reads coalesced along cells, writes coalesced along channels.
__global__ void __launch_bounds__(256)
nchw_to_nhwc_fp16(const float* __restrict__ feat, size_t dst_off, int HW)
{
    __shared__ float tile[32][33];
    int cell0 = blockIdx.x * 32;
    int c0    = blockIdx.y * 32;
    int b     = blockIdx.z;
    int tx = threadIdx.x & 31;
    int ty = threadIdx.x >> 5;          // 0..7
    const float* src = feat + (size_t)b * NCH * HW;
#pragma unroll
    for (int k = 0; k < 4; k++) {
        int cl = ty + k * 8;
        tile[cl][tx] = src[(size_t)(c0 + cl) * HW + cell0 + tx];
    }
    __syncthreads();
    __half* dst = g_nhwc + dst_off + ((size_t)b * HW + cell0) * NCH + c0;
#pragma unroll
    for (int k = 0; k < 4; k++) {
        int row = ty + k * 8;           // local cell
        dst[(size_t)row * NCH + tx] = __float2half(tile[tx][row]);
    }
}

// ---------------------------------------------------------------------------
// Gather: one warp = one output pixel, lanes cover 256 channels (8 fp16 each,
// one 16B load per tap -> dense 512B warp requests). Accumulate fp32, then
// transpose 32px x 256ch through XOR-swizzled smem for coalesced NCHW stores.

#define TAP(ptr, wgt) do {                                                   \
    uint4 _v = __ldg(reinterpret_cast<const uint4*>(ptr));                   \
    const __half2* _h = reinterpret_cast<const __half2*>(&_v);               \
    float2 _a0 = __half22float2(_h[0]); float2 _a1 = __half22float2(_h[1]);  \
    float2 _a2 = __half22float2(_h[2]); float2 _a3 = __half22float2(_h[3]);  \
    acc[0] = fmaf(wgt, _a0.x, acc[0]); acc[1] = fmaf(wgt, _a0.y, acc[1]);    \
    acc[2] = fmaf(wgt, _a1.x, acc[2]); acc[3] = fmaf(wgt, _a1.y, acc[3]);    \
    acc[4] = fmaf(wgt, _a2.x, acc[4]); acc[5] = fmaf(wgt, _a2.y, acc[5]);    \
    acc[6] = fmaf(wgt, _a3.x, acc[6]); acc[7] = fmaf(wgt, _a3.y, acc[7]);    \
} while (0)

template <int P, int H, int W>
__device__ __forceinline__ void gather_level(
    const float* __restrict__ rois, float* __restrict__ out_lvl,
    size_t lvl_off, float scale, int pxbase, int npx, float* __restrict__ sacc)
{
    constexpr int pixels = P * P;
    int tid  = threadIdx.x;
    int wid  = tid >> 5;
    int lane = tid & 31;

    for (int j = 0; j < 4; j++) {
        int pxl = j * 8 + wid;          // 0..31 local pixel slot
        int gpx = pxbase + pxl;         // level-local pixel index
        float acc[8] = {0.f,0.f,0.f,0.f,0.f,0.f,0.f,0.f};
        if (gpx < npx) {
            int n  = gpx / pixels;
            int p  = gpx - n * pixels;
            int ph = p / P;
            int pw = p - ph * P;
            const float* r = rois + n * 5;
            int   bi = (int)r[0];
            float x1 = fmaf(r[1], scale, -0.5f);
            float y1 = fmaf(r[2], scale, -0.5f);
            float bw = (fmaf(r[3], scale, -0.5f) - x1) * (1.0f / (float)P);
            float bh = (fmaf(r[4], scale, -0.5f) - y1) * (1.0f / (float)P);
            const __half* img = g_nhwc + lvl_off
                              + (size_t)bi * ((size_t)H * W) * NCH + lane * 8;
#pragma unroll
            for (int iy = 0; iy < 2; iy++) {
#pragma unroll
                for (int ix = 0; ix < 2; ix++) {
                    float yy = fmaf((float)ph + 0.25f + 0.5f * iy, bh, y1);
                    float xx = fmaf((float)pw + 0.25f + 0.5f * ix, bw, x1);
                    bool valid = (yy > -1.f) && (yy < (float)H) &&
                                 (xx > -1.f) && (xx < (float)W);
                    float yc = fminf(fmaxf(yy, 0.f), (float)(H - 1));
                    float xc = fminf(fmaxf(xx, 0.f), (float)(W - 1));
                    int y0 = (int)yc;
                    int x0 = (int)xc;
                    float wy1 = (y0 >= H - 1) ? 1.f : yc - (float)y0;
                    float wx1 = (x0 >= W - 1) ? 1.f : xc - (float)x0;
                    int ya = min(y0, H - 2);
                    int xa = min(x0, W - 2);
                    float ws  = valid ? 0.25f : 0.f;
                    float w00 = (1.f - wy1) * (1.f - wx1) * ws;
                    float w01 = (1.f - wy1) * wx1 * ws;
                    float w10 = wy1 * (1.f - wx1) * ws;
                    float w11 = wy1 * wx1 * ws;
                    const __half* f = img + (size_t)(ya * W + xa) * NCH;
                    TAP(f,                 w00);
                    TAP(f + NCH,           w01);
                    TAP(f + (size_t)W*NCH,       w10);
                    TAP(f + (size_t)(W+1)*NCH,   w11);
                }
            }
        }
        // swizzled STS: row = channel, col = pxl ^ (c>>3); conflict-free
        int col = pxl ^ lane;
#pragma unroll
        for (int i = 0; i < 8; i++)
            sacc[(lane * 8 + i) * 32 + col] = acc[i];
    }
    __syncthreads();

    // store phase: lanes along pixels -> coalesced NCHW writes
    int pxlane = tid & 31;
    int gpx = pxbase + pxlane;
    if (gpx < npx) {
        int n = gpx / pixels;
        int p = gpx - n * pixels;
        float* ob = out_lvl + (size_t)n * NCH * pixels + p;
        int c0 = (tid >> 5) * 32;
#pragma unroll
        for (int i = 0; i < 32; i++) {
            int c = c0 + i;
            ob[(size_t)c * pixels] = sacc[c * 32 + (pxlane ^ ((c >> 3) & 31))];
        }
    }
}

__global__ void __launch_bounds__(256)
roi_gather_kernel(const float* __restrict__ rois, float* __restrict__ out,
                  int N, int nb1, int nb2)
{
    __shared__ float sacc[NCH * 32];
    int blk = blockIdx.x;
    if (blk < nb1) {
        gather_level<28, 256, 256>(rois, out, 0ull, 0.25f,
                                   blk * 32, N * 784, sacc);
    } else if (blk < nb1 + nb2) {
        float* o2 = out + (size_t)N * NCH * 784;
        gather_level<14, 128, 128>(rois, o2, 33554432ull, 0.125f,
                                   (blk - nb1) * 32, N * 196, sacc);
    } else {
        float* o3 = out + (size_t)N * NCH * (784 + 196);
        gather_level<7, 64, 64>(rois, o3, 41943040ull, 0.0625f,
                                (blk - nb1 - nb2) * 32, N * 49, sacc);
    }
}

// ---------------------------------------------------------------------------
extern "C" void kernel_launch(void* const* d_in, const int* in_sizes, int n_in,
                              void* d_out, int out_size)
{
    const float* feat1 = (const float*)d_in[0];  // (2,256,256,256)
    const float* feat2 = (const float*)d_in[1];  // (2,256,128,128)
    const float* feat3 = (const float*)d_in[2];  // (2,256,64,64)
    const float* rois  = (const float*)d_in[3];  // (N,5)
    float* out = (float*)d_out;

    const int N = in_sizes[3] / 5;

    // 1) transpose each level to fp16 NHWC scratch
    {
        dim3 g1(65536 / 32, 8, 2);
        nchw_to_nhwc_fp16<<<g1, 256>>>(feat1, 0ull, 65536);
        dim3 g2(16384 / 32, 8, 2);
        nchw_to_nhwc_fp16<<<g2, 256>>>(feat2, 33554432ull, 16384);
        dim3 g3(4096 / 32, 8, 2);
        nchw_to_nhwc_fp16<<<g3, 256>>>(feat3, 41943040ull, 4096);
    }

    // 2) fused gather over all three levels
    int nb1 = (N * 784 + 31) / 32;
    int nb2 = (N * 196 + 31) / 32;
    int nb3 = (N * 49  + 31) / 32;
    roi_gather_kernel<<<nb1 + nb2 + nb3, 256>>>(rois, out, N, nb1, nb2);
}

// round 4
// speedup vs baseline: 6.6335x; 1.1655x over previous
#include <cuda_runtime.h>
#include <cuda_fp16.h>

#define NCH 256

// fp16 NHWC copies of the three feature maps.
// offsets (halves): L1=0, L2=33554432, L3=41943040, total 44040192 (88MB)
__device__ __half g_nhwc[44040192];

// ---------------------------------------------------------------------------
// NCHW fp32 -> NHWC fp16 transpose. Tile = 64 channels x 32 cells.
// Reads coalesced along cells (128B rows); writes half2 so each warp stores a
// full 128B row of 64 consecutive channels.
__global__ void __launch_bounds__(256)
nchw_to_nhwc_fp16(const float* __restrict__ feat, size_t dst_off, int HW)
{
    __shared__ float tile[64][33];
    int cell0 = blockIdx.x * 32;
    int c0    = blockIdx.y * 64;
    int b     = blockIdx.z;
    int lane = threadIdx.x & 31;
    int wid  = threadIdx.x >> 5;        // 0..7
    const float* src = feat + (size_t)b * NCH * HW;
#pragma unroll
    for (int k = 0; k < 8; k++) {
        int r = wid + k * 8;            // channel row 0..63
        tile[r][lane] = src[(size_t)(c0 + r) * HW + cell0 + lane];
    }
    __syncthreads();
    __half2* dst2 = reinterpret_cast<__half2*>(g_nhwc + dst_off);
#pragma unroll
    for (int it = 0; it < 4; it++) {
        int cell = wid * 4 + it;        // local cell 0..31
        __half2 h = __floats2half2_rn(tile[2 * lane][cell],
                                      tile[2 * lane + 1][cell]);
        dst2[(((size_t)b * HW + cell0 + cell) * NCH + c0) / 2 + lane] = h;
    }
}

// ---------------------------------------------------------------------------
// Gather: one warp = one output pixel, lanes cover 256 channels (8 fp16 each;
// one 16B load per tap = dense 512B warp request). The 4 taps of each
// bilinear sample accumulate in __half2 (HFMA2), widened to fp32 once per
// sample. Results transposed through XOR-swizzled smem for coalesced NCHW
// stores.

#define TAPH(ptr, wh, s0, s1, s2, s3) do {                                   \
    uint4 _v = __ldg(reinterpret_cast<const uint4*>(ptr));                   \
    const __half2* _h = reinterpret_cast<const __half2*>(&_v);               \
    s0 = __hfma2(wh, _h[0], s0); s1 = __hfma2(wh, _h[1], s1);                \
    s2 = __hfma2(wh, _h[2], s2); s3 = __hfma2(wh, _h[3], s3);                \
} while (0)

template <int P, int H, int W>
__device__ __forceinline__ void gather_level(
    const float* __restrict__ rois, float* __restrict__ out_lvl,
    size_t lvl_off, float scale, int pxbase, int npx, float* __restrict__ sacc)
{
    constexpr int pixels = P * P;
    int tid  = threadIdx.x;
    int wid  = tid >> 5;
    int lane = tid & 31;

    for (int j = 0; j < 4; j++) {
        int pxl = j * 8 + wid;          // 0..31 local pixel slot
        int gpx = pxbase + pxl;         // level-local pixel index
        float acc[8] = {0.f,0.f,0.f,0.f,0.f,0.f,0.f,0.f};
        if (gpx < npx) {
            int n  = gpx / pixels;
            int p  = gpx - n * pixels;
            int ph = p / P;
            int pw = p - ph * P;
            const float* r = rois + n * 5;
            int   bi = (int)r[0];
            float x1 = fmaf(r[1], scale, -0.5f);
            float y1 = fmaf(r[2], scale, -0.5f);
            float bw = (fmaf(r[3], scale, -0.5f) - x1) * (1.0f / (float)P);
            float bh = (fmaf(r[4], scale, -0.5f) - y1) * (1.0f / (float)P);
            const __half* img = g_nhwc + lvl_off
                              + (size_t)bi * ((size_t)H * W) * NCH + lane * 8;
#pragma unroll
            for (int iy = 0; iy < 2; iy++) {
#pragma unroll
                for (int ix = 0; ix < 2; ix++) {
                    float yy = fmaf((float)ph + 0.25f + 0.5f * iy, bh, y1);
                    float xx = fmaf((float)pw + 0.25f + 0.5f * ix, bw, x1);
                    bool valid = (yy > -1.f) && (yy < (float)H) &&
                                 (xx > -1.f) && (xx < (float)W);
                    float yc = fminf(fmaxf(yy, 0.f), (float)(H - 1));
                    float xc = fminf(fmaxf(xx, 0.f), (float)(W - 1));
                    int y0 = (int)yc;
                    int x0 = (int)xc;
                    float wy1 = (y0 >= H - 1) ? 1.f : yc - (float)y0;
                    float wx1 = (x0 >= W - 1) ? 1.f : xc - (float)x0;
                    int ya = min(y0, H - 2);
                    int xa = min(x0, W - 2);
                    float ws  = valid ? 0.25f : 0.f;
                    __half2 w00 = __float2half2_rn((1.f - wy1) * (1.f - wx1) * ws);
                    __half2 w01 = __float2half2_rn((1.f - wy1) * wx1 * ws);
                    __half2 w10 = __float2half2_rn(wy1 * (1.f - wx1) * ws);
                    __half2 w11 = __float2half2_rn(wy1 * wx1 * ws);
                    const __half* f = img + (size_t)(ya * W + xa) * NCH;
                    __half2 z = __float2half2_rn(0.f);
                    __half2 s0 = z, s1 = z, s2 = z, s3 = z;
                    TAPH(f,                       w00, s0, s1, s2, s3);
                    TAPH(f + NCH,                 w01, s0, s1, s2, s3);
                    TAPH(f + (size_t)W * NCH,     w10, s0, s1, s2, s3);
                    TAPH(f + (size_t)(W+1) * NCH, w11, s0, s1, s2, s3);
                    float2 f0 = __half22float2(s0);
                    float2 f1 = __half22float2(s1);
                    float2 f2 = __half22float2(s2);
                    float2 f3 = __half22float2(s3);
                    acc[0] += f0.x; acc[1] += f0.y;
                    acc[2] += f1.x; acc[3] += f1.y;
                    acc[4] += f2.x; acc[5] += f2.y;
                    acc[6] += f3.x; acc[7] += f3.y;
                }
            }
        }
        // swizzled STS: row = channel, col = pxl ^ (c>>3); conflict-free
        int col = pxl ^ lane;
#pragma unroll
        for (int i = 0; i < 8; i++)
            sacc[(lane * 8 + i) * 32 + col] = acc[i];
    }
    __syncthreads();

    // store phase: lanes along pixels -> coalesced NCHW writes
    int pxlane = tid & 31;
    int gpx = pxbase + pxlane;
    if (gpx < npx) {
        int n = gpx / pixels;
        int p = gpx - n * pixels;
        float* ob = out_lvl + (size_t)n * NCH * pixels + p;
        int c0 = (tid >> 5) * 32;
#pragma unroll
        for (int i = 0; i < 32; i++) {
            int c = c0 + i;
            ob[(size_t)c * pixels] = sacc[c * 32 + (pxlane ^ ((c >> 3) & 31))];
        }
    }
}

__global__ void __launch_bounds__(256)
roi_gather_kernel(const float* __restrict__ rois, float* __restrict__ out,
                  int N, int nb1, int nb2)
{
    __shared__ float sacc[NCH * 32];
    int blk = blockIdx.x;
    if (blk < nb1) {
        gather_level<28, 256, 256>(rois, out, 0ull, 0.25f,
                                   blk * 32, N * 784, sacc);
    } else if (blk < nb1 + nb2) {
        float* o2 = out + (size_t)N * NCH * 784;
        gather_level<14, 128, 128>(rois, o2, 33554432ull, 0.125f,
                                   (blk - nb1) * 32, N * 196, sacc);
    } else {
        float* o3 = out + (size_t)N * NCH * (784 + 196);
        gather_level<7, 64, 64>(rois, o3, 41943040ull, 0.0625f,
                                (blk - nb1 - nb2) * 32, N * 49, sacc);
    }
}

// ---------------------------------------------------------------------------
extern "C" void kernel_launch(void* const* d_in, const int* in_sizes, int n_in,
                              void* d_out, int out_size)
{
    const float* feat1 = (const float*)d_in[0];  // (2,256,256,256)
    const float* feat2 = (const float*)d_in[1];  // (2,256,128,128)
    const float* feat3 = (const float*)d_in[2];  // (2,256,64,64)
    const float* rois  = (const float*)d_in[3];  // (N,5)
    float* out = (float*)d_out;

    const int N = in_sizes[3] / 5;

    // 1) transpose each level to fp16 NHWC scratch
    {
        dim3 g1(65536 / 32, 4, 2);
        nchw_to_nhwc_fp16<<<g1, 256>>>(feat1, 0ull, 65536);
        dim3 g2(16384 / 32, 4, 2);
        nchw_to_nhwc_fp16<<<g2, 256>>>(feat2, 33554432ull, 16384);
        dim3 g3(4096 / 32, 4, 2);
        nchw_to_nhwc_fp16<<<g3, 256>>>(feat3, 41943040ull, 4096);
    }

    // 2) fused gather over all three levels
    int nb1 = (N * 784 + 31) / 32;
    int nb2 = (N * 196 + 31) / 32;
    int nb3 = (N * 49  + 31) / 32;
    roi_gather_kernel<<<nb1 + nb2 + nb3, 256>>>(rois, out, N, nb1, nb2);
}